// round 7
// baseline (speedup 1.0000x reference)
#include <cuda_runtime.h>
#include <math.h>

// Problem constants (fixed by reference setup_inputs)
#define N_BATCH 256
#define M_ROWS  8
#define T_LEN   16384
#define THREADS 512
#define NWARPS  (THREADS / 32)
#define TV      (T_LEN / 4)              // 4096 float4 per row
#define ITERS   (TV / THREADS)           // 8
#define NACC    30                       // band |m-k| <= 4 of the 8x8 Gram

// band layout: acc[c_off(d) + k] holds sum_t X[k+d][t] * X[k][t]
__host__ __device__ __forceinline__ constexpr int c_off(int d) {
    return (d == 0) ? 0 : (d == 1) ? 8 : (d == 2) ? 15 : (d == 3) ? 21 : 26;
}

__global__ void __launch_bounds__(THREADS)
ssf_kernel(const float* __restrict__ X, float* __restrict__ out) {
    __shared__ float sred[NWARPS][NACC];
    __shared__ float sC[NACC];

    const int n   = blockIdx.x;
    const int tid = threadIdx.x;

    const float4* __restrict__ base =
        reinterpret_cast<const float4*>(X + (size_t)n * M_ROWS * T_LEN);

    float acc[NACC];
#pragma unroll
    for (int i = 0; i < NACC; i++) acc[i] = 0.f;

    // ---- software-pipelined main loop: loads for iter i+1 issued before
    //      compute of iter i, so LDGs stay in flight during the FMA phase ----
    float4 cur[M_ROWS], nxt[M_ROWS];
#pragma unroll
    for (int m = 0; m < M_ROWS; m++)
        cur[m] = base[m * TV + tid];

#pragma unroll
    for (int it = 0; it < ITERS; it++) {
        if (it + 1 < ITERS) {
            const int tv = tid + (it + 1) * THREADS;
#pragma unroll
            for (int m = 0; m < M_ROWS; m++)
                nxt[m] = base[m * TV + tv];
        }

#pragma unroll
        for (int m = 0; m < M_ROWS; m++) {
            const int dmax = (m < 4) ? m : 4;
#pragma unroll
            for (int d = 0; d <= dmax; d++) {
                const int ai = c_off(d) + (m - d);
                acc[ai] = fmaf(cur[m].x, cur[m - d].x, acc[ai]);
                acc[ai] = fmaf(cur[m].y, cur[m - d].y, acc[ai]);
                acc[ai] = fmaf(cur[m].z, cur[m - d].z, acc[ai]);
                acc[ai] = fmaf(cur[m].w, cur[m - d].w, acc[ai]);
            }
        }

#pragma unroll
        for (int m = 0; m < M_ROWS; m++)
            cur[m] = nxt[m];            // register rename; free after unroll
    }

    // ---- reduce 30 sums across the CTA ----
#pragma unroll
    for (int i = 0; i < NACC; i++) {
#pragma unroll
        for (int off = 16; off > 0; off >>= 1)
            acc[i] += __shfl_down_sync(0xffffffffu, acc[i], off);
    }

    const int warp = tid >> 5;
    const int lane = tid & 31;
    if (lane == 0) {
#pragma unroll
        for (int i = 0; i < NACC; i++) sred[warp][i] = acc[i];
    }
    __syncthreads();

    if (tid < NACC) {
        float s = 0.f;
#pragma unroll
        for (int w = 0; w < NWARPS; w++) s += sred[w][tid];
        sC[tid] = s * (1.0f / (float)T_LEN);   // banded C = Gram / T
    }
    __syncthreads();

    if (tid == 0) {
        // tri(s1,s2) = 1/4 * sum_j C[j+s2][j+s1] = 1/4 * sum_j band[d][j+s1],
        // d = s2-s1, in jnp.triu_indices(5) row-major order.
        float tri[15];
        int p = 0;
#pragma unroll
        for (int s1 = 0; s1 < 5; s1++) {
#pragma unroll
            for (int s2 = s1; s2 < 5; s2++) {
                const int d = s2 - s1;
                float r = 0.f;
#pragma unroll
                for (int j = 0; j < 4; j++)
                    r += sC[c_off(d) + j + s1];
                tri[p++] = r * 0.25f;
            }
        }

        // feat = [tri (15), zeros (15)]; standardize over all 30 (pop. std)
        float mean = 0.f;
#pragma unroll
        for (int i = 0; i < 15; i++) mean += tri[i];
        mean *= (1.0f / 30.0f);

        float var = 0.f;
#pragma unroll
        for (int i = 0; i < 15; i++) {
            const float dd = tri[i] - mean;
            var += dd * dd;
        }
        var += 15.0f * mean * mean;    // 15 zero entries contribute mean^2
        var *= (1.0f / 30.0f);

        const float inv = 1.0f / (sqrtf(var) + 1e-8f);

        float* o = out + n * 30;
#pragma unroll
        for (int i = 0; i < 15; i++) o[i] = (tri[i] - mean) * inv;
        const float zval = -mean * inv;
#pragma unroll
        for (int i = 15; i < 30; i++) o[i] = zval;
    }
}

extern "C" void kernel_launch(void* const* d_in, const int* in_sizes, int n_in,
                              void* d_out, int out_size) {
    const float* X = (const float*)d_in[0];
    float* out = (float*)d_out;
    ssf_kernel<<<N_BATCH, THREADS>>>(X, out);
}

// round 8
// speedup vs baseline: 1.1659x; 1.1659x over previous
#include <cuda_runtime.h>
#include <math.h>

// Problem constants (fixed by reference setup_inputs)
#define N_BATCH 256
#define M_ROWS  8
#define T_LEN   16384
#define NPAIRS  36          // 8*9/2 lower-tri (symmetric Gram)
#define THREADS 512
#define NWARPS  (THREADS / 32)
#define T4      (T_LEN / 4)              // 4096 float4 per row
#define CHUNKS  2                        // time-chunks per outer iteration
#define ITERS   (T4 / (THREADS * CHUNKS))  // 4

__device__ __forceinline__ int cidx(int a, int b) {
    const int m = a > b ? a : b;
    const int k = a > b ? b : a;
    return m * (m + 1) / 2 + k;
}

__global__ void __launch_bounds__(THREADS)
ssf_fused_kernel(const float* __restrict__ X, float* __restrict__ out) {
    const int n   = blockIdx.x;
    const int tid = threadIdx.x;

    const float4* __restrict__ base =
        reinterpret_cast<const float4*>(X + (size_t)n * M_ROWS * T_LEN);

    float acc[NPAIRS];
#pragma unroll
    for (int i = 0; i < NPAIRS; i++) acc[i] = 0.f;

#pragma unroll
    for (int it = 0; it < ITERS; it++) {
        const int t4a = tid + it * (THREADS * CHUNKS);
        const int t4b = t4a + THREADS;

        // 16 LDG.128 issued back-to-back: 2x the in-flight bytes of R2
        float4 va[M_ROWS], vb[M_ROWS];
#pragma unroll
        for (int m = 0; m < M_ROWS; m++)
            va[m] = base[m * T4 + t4a];
#pragma unroll
        for (int m = 0; m < M_ROWS; m++)
            vb[m] = base[m * T4 + t4b];

        int idx = 0;
#pragma unroll
        for (int m = 0; m < M_ROWS; m++) {
#pragma unroll
            for (int k = 0; k <= m; k++) {
                acc[idx] = fmaf(va[m].x, va[k].x, acc[idx]);
                acc[idx] = fmaf(va[m].y, va[k].y, acc[idx]);
                acc[idx] = fmaf(va[m].z, va[k].z, acc[idx]);
                acc[idx] = fmaf(va[m].w, va[k].w, acc[idx]);
                acc[idx] = fmaf(vb[m].x, vb[k].x, acc[idx]);
                acc[idx] = fmaf(vb[m].y, vb[k].y, acc[idx]);
                acc[idx] = fmaf(vb[m].z, vb[k].z, acc[idx]);
                acc[idx] = fmaf(vb[m].w, vb[k].w, acc[idx]);
                idx++;
            }
        }
    }

    // Intra-warp tree reduce for each of the 36 sums
#pragma unroll
    for (int i = 0; i < NPAIRS; i++) {
#pragma unroll
        for (int off = 16; off > 0; off >>= 1)
            acc[i] += __shfl_down_sync(0xffffffffu, acc[i], off);
    }

    __shared__ float sred[NWARPS][NPAIRS];
    __shared__ float sC[NPAIRS];
    const int warp = tid >> 5;
    const int lane = tid & 31;
    if (lane == 0) {
#pragma unroll
        for (int i = 0; i < NPAIRS; i++) sred[warp][i] = acc[i];
    }
    __syncthreads();

    if (tid < NPAIRS) {
        float s = 0.f;
#pragma unroll
        for (int w = 0; w < NWARPS; w++) s += sred[w][tid];
        sC[tid] = s * (1.0f / (float)T_LEN);   // C = Gram / T
    }
    __syncthreads();

    if (tid == 0) {
        // R[s1][s2] = mean over j of C[j+s1][j+s2]; upper triangle in
        // jnp.triu_indices(5) (row-major) order.
        float tri[15];
        int p = 0;
#pragma unroll
        for (int s1 = 0; s1 < 5; s1++) {
#pragma unroll
            for (int s2 = s1; s2 < 5; s2++) {
                float r = 0.f;
#pragma unroll
                for (int j = 0; j < 4; j++)
                    r += sC[cidx(j + s1, j + s2)];
                tri[p++] = r * 0.25f;
            }
        }

        // feat = [tri (15), zeros (15)]; standardize over all 30 (pop. std)
        float mean = 0.f;
#pragma unroll
        for (int i = 0; i < 15; i++) mean += tri[i];
        mean *= (1.0f / 30.0f);

        float var = 0.f;
#pragma unroll
        for (int i = 0; i < 15; i++) {
            const float d = tri[i] - mean;
            var += d * d;
        }
        var += 15.0f * mean * mean;   // 15 zero entries each contribute mean^2
        var *= (1.0f / 30.0f);

        const float inv = 1.0f / (sqrtf(var) + 1e-8f);

        float* o = out + n * 30;
#pragma unroll
        for (int i = 0; i < 15; i++) o[i] = (tri[i] - mean) * inv;
        const float zval = -mean * inv;
#pragma unroll
        for (int i = 15; i < 30; i++) o[i] = zval;
    }
}

extern "C" void kernel_launch(void* const* d_in, const int* in_sizes, int n_in,
                              void* d_out, int out_size) {
    const float* X = (const float*)d_in[0];
    float* out = (float*)d_out;
    ssf_fused_kernel<<<N_BATCH, THREADS>>>(X, out);
}